// round 14
// baseline (speedup 1.0000x reference)
#include <cuda_runtime.h>
#include <cuda_fp16.h>
#include <math.h>
#include <stdint.h>

// ---------------- scratch (static device globals; no allocation) ----------------
__device__ uint32_t g_kp [(size_t)4 * 8 * 1024 * 16];  // [b][h][m][16 half2] K frag-perm
__device__ uint32_t g_vp [(size_t)4 * 8 * 16 * 1024];  // [b][h][ci][d][32 half2] V frag-perm
__device__ float    g_vt [(size_t)4 * 256 * 1024];     // [b][c][m] fp32 planar v
__device__ float    g_vpe[(size_t)4 * 1024 * 256];     // [b][m][c]
__device__ float    g_pre[(size_t)4 * 4096 * 256];     // [b][n][c]  attention output

// ---------------- helpers ----------------
__device__ __forceinline__ void mma_fp16(float c[4], const uint32_t a[4],
                                         uint32_t b0, uint32_t b1) {
    asm("mma.sync.aligned.m16n8k16.row.col.f32.f16.f16.f32 "
        "{%0,%1,%2,%3}, {%4,%5,%6,%7}, {%8,%9}, {%0,%1,%2,%3};"
        : "+f"(c[0]), "+f"(c[1]), "+f"(c[2]), "+f"(c[3])
        : "r"(a[0]), "r"(a[1]), "r"(a[2]), "r"(a[3]), "r"(b0), "r"(b1));
}
__device__ __forceinline__ uint32_t packh2(float a, float b) {
    __half2 h = __floats2half2_rn(a, b);
    return *(uint32_t*)&h;
}
__device__ __forceinline__ uint32_t h2exp2(uint32_t x) {
    uint32_t r; asm("ex2.approx.f16x2 %0, %1;" : "=r"(r) : "r"(x)); return r;
}

// q pre-scale: 1/sqrt(32) * log2(e), folded so attention uses raw ex2
#define QPRESCALE ((float)(0.17677669529663687 * 1.4426950408889634))

// =================================================================================
// fp16 conv1x1 (kv only now), input planar [C][Nsp], tile 128n x 64o.
// Writes K/V fragment-permuted fp16 buffers + fp32 planar v.
// =================================================================================
__global__ __launch_bounds__(256) void k_conv_fp16_kv(
    const float* __restrict__ X, const float* __restrict__ W,
    const float* __restrict__ scale, const float* __restrict__ bias,
    uint32_t* __restrict__ kp, uint32_t* __restrict__ vp,
    float* __restrict__ vt, int C, int Nsp)
{
    __shared__ __align__(16) uint32_t As[16 * 136];
    __shared__ __align__(16) uint32_t Ws[64 * 20];
    const int b  = blockIdx.z;
    const int n0 = blockIdx.y * 128;
    const int o0 = blockIdx.x * 64;
    const int tid = threadIdx.x;
    const int warp = tid >> 5, lane = tid & 31;
    const int gid = lane >> 2, tig = lane & 3;
    const int wm = warp * 16;

    const float* Xb = X + (size_t)b * C * Nsp;
    float Cacc[8][4];
    #pragma unroll
    for (int i = 0; i < 8; i++)
        #pragma unroll
        for (int j = 0; j < 4; j++) Cacc[i][j] = 0.0f;

    float4 ra[2][2], rb[2];
    #pragma unroll
    for (int i = 0; i < 2; i++) {
        int idx = tid + 256 * i;
        int kw = idx >> 5, m4 = (idx & 31) * 4;
        ra[i][0] = *(const float4*)&Xb[(size_t)(2 * kw)     * Nsp + n0 + m4];
        ra[i][1] = *(const float4*)&Xb[(size_t)(2 * kw + 1) * Nsp + n0 + m4];
    }
    #pragma unroll
    for (int i = 0; i < 2; i++) {
        int idx = tid + 256 * i;
        int o = idx >> 3, kq = (idx & 7) * 4;
        rb[i] = *(const float4*)&W[(size_t)(o0 + o) * C + kq];
    }

    for (int c0 = 0; c0 < C; c0 += 32) {
        #pragma unroll
        for (int i = 0; i < 2; i++) {
            int idx = tid + 256 * i;
            int kw = idx >> 5, m4 = (idx & 31) * 4;
            uint4 u;
            u.x = packh2(ra[i][0].x, ra[i][1].x);
            u.y = packh2(ra[i][0].y, ra[i][1].y);
            u.z = packh2(ra[i][0].z, ra[i][1].z);
            u.w = packh2(ra[i][0].w, ra[i][1].w);
            *(uint4*)&As[kw * 136 + m4] = u;
        }
        #pragma unroll
        for (int i = 0; i < 2; i++) {
            int idx = tid + 256 * i;
            int o = idx >> 3, kw0 = (idx & 7) * 2;
            uint2 v;
            v.x = packh2(rb[i].x, rb[i].y);
            v.y = packh2(rb[i].z, rb[i].w);
            *(uint2*)&Ws[o * 20 + kw0] = v;
        }
        __syncthreads();
        if (c0 + 32 < C) {
            #pragma unroll
            for (int i = 0; i < 2; i++) {
                int idx = tid + 256 * i;
                int kw = idx >> 5, m4 = (idx & 31) * 4;
                ra[i][0] = *(const float4*)&Xb[(size_t)(c0 + 32 + 2 * kw)     * Nsp + n0 + m4];
                ra[i][1] = *(const float4*)&Xb[(size_t)(c0 + 32 + 2 * kw + 1) * Nsp + n0 + m4];
            }
            #pragma unroll
            for (int i = 0; i < 2; i++) {
                int idx = tid + 256 * i;
                int o = idx >> 3, kq = (idx & 7) * 4;
                rb[i] = *(const float4*)&W[(size_t)(o0 + o) * C + c0 + 32 + kq];
            }
        }
        #pragma unroll
        for (int ks = 0; ks < 2; ks++) {
            int kwb = ks * 8;
            uint32_t aF[4];
            aF[0] = As[(kwb + tig) * 136 + wm + gid];
            aF[1] = As[(kwb + tig) * 136 + wm + gid + 8];
            aF[2] = As[(kwb + tig + 4) * 136 + wm + gid];
            aF[3] = As[(kwb + tig + 4) * 136 + wm + gid + 8];
            #pragma unroll
            for (int nt = 0; nt < 8; nt++) {
                uint32_t b0 = Ws[(nt * 8 + gid) * 20 + kwb + tig];
                uint32_t b1 = Ws[(nt * 8 + gid) * 20 + kwb + tig + 4];
                mma_fp16(Cacc[nt], aF, b0, b1);
            }
        }
        __syncthreads();
    }

    const int nlo = n0 + wm + gid, nhi = nlo + 8;
    #pragma unroll
    for (int nt = 0; nt < 8; nt++) {
        int o = o0 + nt * 8 + 2 * tig;          // even channel
        float2 sc = *(const float2*)&scale[o];
        float2 bi = *(const float2*)&bias[o];
        float2 lo, hi;
        lo.x = Cacc[nt][0] * sc.x + bi.x;
        lo.y = Cacc[nt][1] * sc.y + bi.y;
        hi.x = Cacc[nt][2] * sc.x + bi.x;
        hi.y = Cacc[nt][3] * sc.y + bi.y;

        int h = o >> 6;
        int c = o & 63;
        if (c < 32) {
            int w = ((c & 7) >> 1) * 4 + (((c >> 3) & 1) | (((c >> 4) & 1) << 1));
            size_t base = ((size_t)b * 8 + h) * 1024;
            kp[(base + nlo) * 16 + w] = packh2(lo.x, lo.y);
            kp[(base + nhi) * 16 + w] = packh2(hi.x, hi.y);
        } else {
            int cv = c - 32;
            __half* vph = (__half*)vp;
            size_t bhb = ((size_t)b * 8 + h) * 16 * 1024 * 2;
            #pragma unroll
            for (int sel = 0; sel < 4; sel++) {
                int m = (sel & 2) ? nhi : nlo;
                int d = cv + (sel & 1);
                float v = (sel == 0) ? lo.x : (sel == 1) ? lo.y : (sel == 2) ? hi.x : hi.y;
                int ci = m >> 6, rm = m & 63;
                int pr = rm >> 1, lb = rm & 1;
                int pos = (pr & 3) * 8 + (pr >> 2);
                vph[bhb + (((size_t)ci * 32 + d) * 32 + pos) * 2 + lb] = __float2half_rn(v);
            }
            int vc = h * 32 + cv;
            vt[((size_t)b * 256 + vc)     * Nsp + nlo] = lo.x;
            vt[((size_t)b * 256 + vc + 1) * Nsp + nlo] = lo.y;
            vt[((size_t)b * 256 + vc)     * Nsp + nhi] = hi.x;
            vt[((size_t)b * 256 + vc + 1) * Nsp + nhi] = hi.y;
        }
    }
}

// =================================================================================
// bilerp descriptor for the fused upsample
// =================================================================================
struct Bil { int r00, r01, r10, r11; float w00, w01, w10, w11; };
__device__ __forceinline__ Bil make_bil(int n) {
    int y = n >> 6, x = n & 63;
    float ys = y * 0.5f - 0.25f;
    float xs = x * 0.5f - 0.25f;
    int y0 = (int)floorf(ys), x0 = (int)floorf(xs);
    float wy = ys - (float)y0, wx = xs - (float)x0;
    int y0c = max(y0, 0), y1c = min(y0 + 1, 31);
    int x0c = max(x0, 0), x1c = min(x0 + 1, 31);
    Bil bl;
    bl.r00 = y0c * 32 + x0c; bl.r01 = y0c * 32 + x1c;
    bl.r10 = y1c * 32 + x0c; bl.r11 = y1c * 32 + x1c;
    bl.w00 = (1.f - wy) * (1.f - wx); bl.w01 = (1.f - wy) * wx;
    bl.w10 = wy * (1.f - wx);         bl.w11 = wy * wx;
    return bl;
}
__device__ __forceinline__ float4 fused_pre_load(
    const float* __restrict__ pre_row, const float* __restrict__ vb,
    const Bil& bl, int cq)
{
    float4 t   = *(const float4*)&pre_row[cq];
    float4 v00 = *(const float4*)&vb[bl.r00 * 256 + cq];
    float4 v01 = *(const float4*)&vb[bl.r01 * 256 + cq];
    float4 v10 = *(const float4*)&vb[bl.r10 * 256 + cq];
    float4 v11 = *(const float4*)&vb[bl.r11 * 256 + cq];
    t.x += bl.w00 * v00.x + bl.w01 * v01.x + bl.w10 * v10.x + bl.w11 * v11.x;
    t.y += bl.w00 * v00.y + bl.w01 * v01.y + bl.w10 * v10.y + bl.w11 * v11.y;
    t.z += bl.w00 * v00.z + bl.w01 * v01.z + bl.w10 * v10.z + bl.w11 * v11.z;
    t.w += bl.w00 * v00.w + bl.w01 * v01.w + bl.w10 * v10.w + bl.w11 * v11.w;
    return t;
}

// =================================================================================
// fp16 conv1x1 projection with FUSED upsample+add on the B-tile input.
// =================================================================================
__global__ __launch_bounds__(256) void k_conv_fp16_proj(
    const float* __restrict__ Ain, const float* __restrict__ vpe,
    const float* __restrict__ W,
    const float* __restrict__ scale, const float* __restrict__ bias,
    float* __restrict__ out, int C, int Nsp, int O)
{
    __shared__ __align__(16) uint32_t Wa[128 * 20];
    __shared__ __align__(16) uint32_t Ab[64 * 20];
    const int b  = blockIdx.z;
    const int o0 = blockIdx.x * 128;
    const int n0 = blockIdx.y * 64;
    const int tid = threadIdx.x;
    const int warp = tid >> 5, lane = tid & 31;
    const int gid = lane >> 2, tig = lane & 3;
    const int wm = warp * 16;

    const float* Ainb = Ain + (size_t)b * Nsp * C;
    const float* vb   = vpe + (size_t)b * 1024 * 256;

    const int bn0 = n0 + (tid >> 3);
    const int bn1 = n0 + ((tid + 256) >> 3);
    const Bil bl0 = make_bil(bn0);
    const Bil bl1 = make_bil(bn1);
    const float* prow0 = &Ainb[(size_t)bn0 * C];
    const float* prow1 = &Ainb[(size_t)bn1 * C];
    const int bkq = (tid & 7) * 4;

    float Cacc[8][4];
    #pragma unroll
    for (int i = 0; i < 8; i++)
        #pragma unroll
        for (int j = 0; j < 4; j++) Cacc[i][j] = 0.0f;

    float4 ra[4], rb[2];
    #pragma unroll
    for (int i = 0; i < 4; i++) {
        int idx = tid + 256 * i;
        int o = idx >> 3, kq = (idx & 7) * 4;
        ra[i] = *(const float4*)&W[(size_t)(o0 + o) * C + kq];
    }
    rb[0] = fused_pre_load(prow0, vb, bl0, bkq);
    rb[1] = fused_pre_load(prow1, vb, bl1, bkq);

    for (int c0 = 0; c0 < C; c0 += 32) {
        #pragma unroll
        for (int i = 0; i < 4; i++) {
            int idx = tid + 256 * i;
            int o = idx >> 3, kw0 = (idx & 7) * 2;
            uint2 v;
            v.x = packh2(ra[i].x, ra[i].y);
            v.y = packh2(ra[i].z, ra[i].w);
            *(uint2*)&Wa[o * 20 + kw0] = v;
        }
        #pragma unroll
        for (int i = 0; i < 2; i++) {
            int idx = tid + 256 * i;
            int n = idx >> 3, kw0 = (idx & 7) * 2;
            uint2 v;
            v.x = packh2(rb[i].x, rb[i].y);
            v.y = packh2(rb[i].z, rb[i].w);
            *(uint2*)&Ab[n * 20 + kw0] = v;
        }
        __syncthreads();
        if (c0 + 32 < C) {
            #pragma unroll
            for (int i = 0; i < 4; i++) {
                int idx = tid + 256 * i;
                int o = idx >> 3, kq = (idx & 7) * 4;
                ra[i] = *(const float4*)&W[(size_t)(o0 + o) * C + c0 + 32 + kq];
            }
            rb[0] = fused_pre_load(prow0, vb, bl0, c0 + 32 + bkq);
            rb[1] = fused_pre_load(prow1, vb, bl1, c0 + 32 + bkq);
        }
        #pragma unroll
        for (int ks = 0; ks < 2; ks++) {
            int kwb = ks * 8;
            uint32_t aF[4];
            aF[0] = Wa[(wm + gid) * 20 + kwb + tig];
            aF[1] = Wa[(wm + gid + 8) * 20 + kwb + tig];
            aF[2] = Wa[(wm + gid) * 20 + kwb + tig + 4];
            aF[3] = Wa[(wm + gid + 8) * 20 + kwb + tig + 4];
            #pragma unroll
            for (int nt = 0; nt < 8; nt++) {
                uint32_t b0 = Ab[(nt * 8 + gid) * 20 + kwb + tig];
                uint32_t b1 = Ab[(nt * 8 + gid) * 20 + kwb + tig + 4];
                mma_fp16(Cacc[nt], aF, b0, b1);
            }
        }
        __syncthreads();
    }

    const int olo = o0 + wm + gid, ohi = olo + 8;
    const float sclo = scale[olo], bilo = bias[olo];
    const float schi = scale[ohi], bihi = bias[ohi];
    #pragma unroll
    for (int nt = 0; nt < 8; nt++) {
        int n = n0 + nt * 8 + 2 * tig;
        float2 lo, hi;
        lo.x = Cacc[nt][0] * sclo + bilo;
        lo.y = Cacc[nt][1] * sclo + bilo;
        hi.x = Cacc[nt][2] * schi + bihi;
        hi.y = Cacc[nt][3] * schi + bihi;
        *(float2*)&out[((size_t)b * O + olo) * Nsp + n] = lo;
        *(float2*)&out[((size_t)b * O + ohi) * Nsp + n] = hi;
    }
}

// =================================================================================
// attention with FUSED q-projection prologue.
// The inline q-GEMM's C-fragment layout == QK A-fragment layout -> direct pack.
// pool layout: kv double buffer [K0|K1|V0|V1] = 4352 words; prologue As@4352
// (2176 words) + Ws@6528 (640 words) -> total 7168 words = 28 KB.
// =================================================================================
#define KO(bf) ((bf) * 1024)
#define VO(bf) (2048 + (bf) * 1152)
#define QAS 4352
#define QWS 6528

__global__ __launch_bounds__(256) void k_attn_fp16(
    const float* __restrict__ x, const float* __restrict__ Wq,
    const float* __restrict__ q_scale, const float* __restrict__ q_bias,
    const uint32_t* __restrict__ kp, const uint32_t* __restrict__ vp,
    float* __restrict__ pre)
{
    __shared__ __align__(16) uint32_t pool[7168];

    const int bh = blockIdx.y;
    const int b = bh >> 3, h = bh & 7;
    const int tid = threadIdx.x;
    const int warp = tid >> 5, lane = tid & 31;
    const int gid = lane >> 2, tig = lane & 3;
    const int n0 = blockIdx.x * 128;
    const int wm = warp * 16;
    const int C = 256;

    const uint32_t* kpb = kp + ((size_t)b * 8 + h) * 1024 * 16;
    const uint32_t* vpb = vp + ((size_t)b * 8 + h) * 16 * 1024;

    // issue kv chunk-0 prefetch FIRST; its latency hides under the q prologue
    {
        int rk = tid >> 2, sk = (tid & 3) * 4;
        uint32_t dK = (uint32_t)__cvta_generic_to_shared(&pool[KO(0) + rk * 16 + sk]);
        asm volatile("cp.async.cg.shared.global [%0], [%1], 16;"
                     :: "r"(dK), "l"(&kpb[(size_t)rk * 16 + sk]));
        int dv = tid >> 3, sv = (tid & 7) * 4;
        uint32_t dV = (uint32_t)__cvta_generic_to_shared(&pool[VO(0) + dv * 36 + sv]);
        asm volatile("cp.async.cg.shared.global [%0], [%1], 16;"
                     :: "r"(dV), "l"(&vpb[(size_t)dv * 32 + sv]));
    }
    asm volatile("cp.async.commit_group;" ::: "memory");

    // ================= q-projection prologue: q[128 n x 32 d] =================
    const float* Xb = x + (size_t)b * C * 4096;
    const float* Wqh = Wq + (size_t)(h * 32) * C;
    float Cacc[4][4];
    #pragma unroll
    for (int i = 0; i < 4; i++)
        #pragma unroll
        for (int j = 0; j < 4; j++) Cacc[i][j] = 0.0f;

    float4 ra[2][2], rbq;
    #pragma unroll
    for (int i = 0; i < 2; i++) {
        int idx = tid + 256 * i;
        int kw = idx >> 5, m4 = (idx & 31) * 4;
        ra[i][0] = *(const float4*)&Xb[(size_t)(2 * kw)     * 4096 + n0 + m4];
        ra[i][1] = *(const float4*)&Xb[(size_t)(2 * kw + 1) * 4096 + n0 + m4];
    }
    {
        int o = tid >> 3, kq = (tid & 7) * 4;
        rbq = *(const float4*)&Wqh[(size_t)o * C + kq];
    }

    for (int c0 = 0; c0 < C; c0 += 32) {
        #pragma unroll
        for (int i = 0; i < 2; i++) {
            int idx = tid + 256 * i;
            int kw = idx >> 5, m4 = (idx & 31) * 4;
            uint4 u;
            u.x = packh2(ra[i][0].x, ra[i][1].x);
            u.y = packh2(ra[i][0].y, ra[i][1].y);
            u.z = packh2(ra[i][0].z, ra[i][1].z);
            u.w = packh2(ra[i][0].w, ra[i][1].w);
            *(uint4*)&pool[QAS + kw * 136 + m4] = u;
        }
        {
            int o = tid >> 3, kw0 = (tid & 7) * 2;
            uint2 v;
            v.x = packh2(rbq.x, rbq.y);
            v.y = packh2(rbq.z, rbq.w);
            *(uint2*)&pool[QWS + o * 20 + kw0] = v;
        }
        __syncthreads();
        if (c0 + 32 < C) {
            #pragma unroll
            for (int i = 0; i < 2; i++) {
                int idx = tid + 256 * i;
                int kw = idx >> 5, m4 = (idx & 31) * 4;
                ra[i][0] = *(const float4*)&Xb[(size_t)(c0 + 32 + 2 * kw)     * 4096 + n0 + m4];
                ra[i][1] = *(const float4*)&Xb[(size_t)(c0 + 32 + 2 * kw + 1) * 4096 + n0 + m4];
            }
            int o = tid >> 3, kq = (tid & 7) * 4;
            rbq = *(const float4*)&Wqh[(size_t)o * C + c0 + 32 + kq];
        }
        #pragma unroll
        for (int ks = 0; ks < 2; ks++) {
            int kwb = ks * 8;
            uint32_t aF[4];
            aF[0] = pool[QAS + (kwb + tig) * 136 + wm + gid];
            aF[1] = pool[QAS + (kwb + tig) * 136 + wm + gid + 8];
            aF[2] = pool[QAS + (kwb + tig + 4) * 136 + wm + gid];
            aF[3] = pool[QAS + (kwb + tig + 4) * 136 + wm + gid + 8];
            #pragma unroll
            for (int nt = 0; nt < 4; nt++) {
                uint32_t b0 = pool[QWS + (nt * 8 + gid) * 20 + kwb + tig];
                uint32_t b1 = pool[QWS + (nt * 8 + gid) * 20 + kwb + tig + 4];
                mma_fp16(Cacc[nt], aF, b0, b1);
            }
        }
        __syncthreads();
    }

    // C-frag -> QK A-frag: scale/bias/QPRESCALE, pack. nt{0,1}->qA[0], nt{2,3}->qA[1]
    uint32_t qA[2][4];
    #pragma unroll
    for (int nt = 0; nt < 4; nt++) {
        int d = nt * 8 + 2 * tig;                   // even d
        float2 sc = *(const float2*)&q_scale[h * 32 + d];
        float2 bi = *(const float2*)&q_bias[h * 32 + d];
        uint32_t wlo = packh2((Cacc[nt][0] * sc.x + bi.x) * QPRESCALE,
                              (Cacc[nt][1] * sc.y + bi.y) * QPRESCALE);
        uint32_t whi = packh2((Cacc[nt][2] * sc.x + bi.x) * QPRESCALE,
                              (Cacc[nt][3] * sc.y + bi.y) * QPRESCALE);
        qA[nt >> 1][(nt & 1) * 2 + 0] = wlo;
        qA[nt >> 1][(nt & 1) * 2 + 1] = whi;
    }

    // ================= attention main loop =================
    float O[4][4];
    #pragma unroll
    for (int i = 0; i < 4; i++)
        #pragma unroll
        for (int j = 0; j < 4; j++) O[i][j] = 0.0f;
    float Lacc[4] = {0.f, 0.f, 0.f, 0.f};
    const uint32_t onesB = (gid == 0) ? 0x3C003C00u : 0u;

    for (int ci = 0; ci < 16; ci++) {
        const int cur = ci & 1;
        if (ci < 15) {
            int rk = tid >> 2, sk = (tid & 3) * 4;
            uint32_t dK = (uint32_t)__cvta_generic_to_shared(&pool[KO(cur ^ 1) + rk * 16 + sk]);
            asm volatile("cp.async.cg.shared.global [%0], [%1], 16;"
                         :: "r"(dK), "l"(&kpb[(size_t)((ci + 1) * 64 + rk) * 16 + sk]));
            int dv = tid >> 3, sv = (tid & 7) * 4;
            uint32_t dV = (uint32_t)__cvta_generic_to_shared(&pool[VO(cur ^ 1) + dv * 36 + sv]);
            asm volatile("cp.async.cg.shared.global [%0], [%1], 16;"
                         :: "r"(dV), "l"(&vpb[(size_t)(ci + 1) * 1024 + dv * 32 + sv]));
            asm volatile("cp.async.commit_group;" ::: "memory");
            asm volatile("cp.async.wait_group 1;" ::: "memory");
        } else {
            asm volatile("cp.async.wait_group 0;" ::: "memory");
        }
        __syncthreads();

        const uint32_t* Kc = &pool[KO(cur)];
        const uint32_t* Vc = &pool[VO(cur)];
        uint4 vr[4];
        #pragma unroll
        for (int g = 0; g < 4; g++) {
            uint4 kwA = *(const uint4*)&Kc[((2 * g) * 8 + gid) * 16 + tig * 4];
            uint4 kwB = *(const uint4*)&Kc[((2 * g + 1) * 8 + gid) * 16 + tig * 4];
            float S0[4] = {0.f, 0.f, 0.f, 0.f};
            float S1[4] = {0.f, 0.f, 0.f, 0.f};
            mma_fp16(S0, qA[0], kwA.x, kwA.y);
            mma_fp16(S0, qA[1], kwA.z, kwA.w);
            mma_fp16(S1, qA[0], kwB.x, kwB.y);
            mma_fp16(S1, qA[1], kwB.z, kwB.w);
            uint32_t pA[4];
            pA[0] = h2exp2(packh2(S0[0], S0[1]));
            pA[1] = h2exp2(packh2(S0[2], S0[3]));
            pA[2] = h2exp2(packh2(S1[0], S1[1]));
            pA[3] = h2exp2(packh2(S1[2], S1[3]));
            mma_fp16(Lacc, pA, onesB, onesB);
            if ((g & 1) == 0) {
                #pragma unroll
                for (int mt = 0; mt < 4; mt++)
                    vr[mt] = *(const uint4*)&Vc[(mt * 8 + gid) * 36 + tig * 8 + 2 * g];
                #pragma unroll
                for (int mt = 0; mt < 4; mt++)
                    mma_fp16(O[mt], pA, vr[mt].x, vr[mt].y);
            } else {
                #pragma unroll
                for (int mt = 0; mt < 4; mt++)
                    mma_fp16(O[mt], pA, vr[mt].z, vr[mt].w);
            }
        }
        __syncthreads();
    }

    float l_lo = __shfl_sync(0xFFFFFFFFu, Lacc[0], lane & ~3);
    float l_hi = __shfl_sync(0xFFFFFFFFu, Lacc[2], lane & ~3);
    float inv_lo = 1.0f / l_lo;
    float inv_hi = 1.0f / l_hi;

    const int rlo = n0 + wm + gid;
    const int rhi = rlo + 8;
    #pragma unroll
    for (int mt = 0; mt < 4; mt++) {
        int c = h * 32 + mt * 8 + 2 * tig;
        float2 lo = make_float2(O[mt][0] * inv_lo, O[mt][1] * inv_lo);
        float2 hi = make_float2(O[mt][2] * inv_hi, O[mt][3] * inv_hi);
        *(float2*)&pre[((size_t)b * 4096 + rlo) * 256 + c] = lo;
        *(float2*)&pre[((size_t)b * 4096 + rhi) * 256 + c] = hi;
    }
}

// =================================================================================
// depthwise 7x7 conv (pad 3), planar v input -> g_vpe[b][m][c]
// =================================================================================
__global__ __launch_bounds__(256) void k_dwconv(
    const float* __restrict__ vt, const float* __restrict__ Wpe,
    const float* __restrict__ pe_scale, const float* __restrict__ pe_bias,
    float* __restrict__ vpe)
{
    __shared__ float plane[1024];
    __shared__ float wsm[49];
    const int c = blockIdx.x;
    const int b = blockIdx.y;
    const int tid = threadIdx.x;

    *(float4*)&plane[tid * 4] = *(const float4*)&vt[((size_t)b * 256 + c) * 1024 + tid * 4];
    if (tid < 49) wsm[tid] = Wpe[c * 49 + tid];
    __syncthreads();

    const float sc = pe_scale[c], bi = pe_bias[c];
    #pragma unroll
    for (int i = 0; i < 4; i++) {
        int m = tid + 256 * i;
        int y = m >> 5, x = m & 31;
        float s = 0.0f;
        #pragma unroll
        for (int ky = 0; ky < 7; ky++) {
            int iy = y + ky - 3;
            if ((unsigned)iy < 32u) {
                #pragma unroll
                for (int kx = 0; kx < 7; kx++) {
                    int ix = x + kx - 3;
                    if ((unsigned)ix < 32u) s += plane[iy * 32 + ix] * wsm[ky * 7 + kx];
                }
            }
        }
        vpe[((size_t)b * 1024 + m) * 256 + c] = s * sc + bi;
    }
}

// =================================================================================
// launch
// =================================================================================
extern "C" void kernel_launch(void* const* d_in, const int* in_sizes, int n_in,
                              void* d_out, int out_size)
{
    (void)in_sizes; (void)n_in; (void)out_size;
    const float* x          = (const float*)d_in[0];
    const float* upper_feat = (const float*)d_in[1];
    const float* Wq         = (const float*)d_in[2];
    const float* q_scale    = (const float*)d_in[3];
    const float* q_bias     = (const float*)d_in[4];
    const float* Wkv        = (const float*)d_in[5];
    const float* kv_scale   = (const float*)d_in[6];
    const float* kv_bias    = (const float*)d_in[7];
    const float* Wpe        = (const float*)d_in[8];
    const float* pe_scale   = (const float*)d_in[9];
    const float* pe_bias    = (const float*)d_in[10];
    const float* Wproj      = (const float*)d_in[11];
    const float* proj_scale = (const float*)d_in[12];
    const float* proj_bias  = (const float*)d_in[13];
    float* out = (float*)d_out;

    float *pvt, *pvpe, *ppre;
    uint32_t *pkp, *pvp;
    cudaGetSymbolAddress((void**)&pkp,  g_kp);
    cudaGetSymbolAddress((void**)&pvp,  g_vp);
    cudaGetSymbolAddress((void**)&pvt,  g_vt);
    cudaGetSymbolAddress((void**)&pvpe, g_vpe);
    cudaGetSymbolAddress((void**)&ppre, g_pre);

    static cudaStream_t s2 = nullptr;
    static cudaEvent_t e_fork = nullptr, e_kv = nullptr, e_dw = nullptr;
    if (s2 == nullptr) {
        cudaStreamCreateWithFlags(&s2, cudaStreamNonBlocking);
        cudaEventCreateWithFlags(&e_fork, cudaEventDisableTiming);
        cudaEventCreateWithFlags(&e_kv,   cudaEventDisableTiming);
        cudaEventCreateWithFlags(&e_dw,   cudaEventDisableTiming);
    }

    // fork
    cudaEventRecord(e_fork, 0);
    cudaStreamWaitEvent(s2, e_fork, 0);

    // stream 2: kv conv -> dwconv
    k_conv_fp16_kv<<<dim3(8, 8, 4), 256, 0, s2>>>(
        upper_feat, Wkv, kv_scale, kv_bias, pkp, pvp, pvt, 256, 1024);
    cudaEventRecord(e_kv, s2);
    k_dwconv<<<dim3(256, 4), 256, 0, s2>>>(pvt, Wpe, pe_scale, pe_bias, pvpe);
    cudaEventRecord(e_dw, s2);

    // main stream: attention with fused q projection (needs kv)
    cudaStreamWaitEvent(0, e_kv, 0);
    k_attn_fp16<<<dim3(32, 32), 256>>>(x, Wq, q_scale, q_bias, pkp, pvp, ppre);

    // join: proj needs attention (stream order) + dwconv (event); upsample fused
    cudaStreamWaitEvent(0, e_dw, 0);
    k_conv_fp16_proj<<<dim3(2, 64, 4), 256>>>(
        ppre, pvpe, Wproj, proj_scale, proj_bias, out, 256, 4096, 256);
}